// round 1
// baseline (speedup 1.0000x reference)
#include <cuda_runtime.h>
#include <cuda_bf16.h>
#include <cstdint>

#define NN 50000
#define EE 600000
#define HH 128
#define GG 2048
#define NBLK 49   // ceil(50000/1024)

// ---------------- scratch (static device globals: no allocation) ----------------
__device__ float g_h[NN * HH];     // GEMM output
__device__ float g_agg[NN * HH];   // aggregated (conv output)
__device__ float g_act[NN * HH];   // BN+ReLU output (next layer input)
__device__ float g_dis[NN];        // deg^-1/2 (incl self loop)
__device__ int   g_deg[NN];
__device__ int   g_rowstart[NN + 1];
__device__ int   g_cursor[NN];
__device__ int   g_esrc[EE];       // CSR (by dst): source node per slot
__device__ float g_ecoef[EE];      // dis[src]*dis[dst] per slot
__device__ int   g_partial[64];
__device__ float g_sum[HH], g_sumsq[HH], g_scale[HH], g_shift[HH];
__device__ int   g_gstart[GG], g_gend[GG];
__device__ float g_z[GG * 2 * HH]; // pooled [mean | max]

// ---------------- degree / CSR build ----------------
__global__ void k_zero_deg() {
    int i = blockIdx.x * blockDim.x + threadIdx.x;
    if (i < NN) g_deg[i] = 0;
}

__global__ void k_deg(const int* __restrict__ dst) {
    int e = blockIdx.x * blockDim.x + threadIdx.x;
    if (e < EE) atomicAdd(&g_deg[dst[e]], 1);
}

__global__ void k_dis() {
    int i = blockIdx.x * blockDim.x + threadIdx.x;
    if (i < NN) g_dis[i] = rsqrtf((float)g_deg[i] + 1.0f);
}

__global__ void k_scan1() {
    __shared__ int sm[1024];
    int tid = threadIdx.x;
    int i = blockIdx.x * 1024 + tid;
    sm[tid] = (i < NN) ? g_deg[i] : 0;
    __syncthreads();
    for (int o = 512; o > 0; o >>= 1) {
        if (tid < o) sm[tid] += sm[tid + o];
        __syncthreads();
    }
    if (tid == 0) g_partial[blockIdx.x] = sm[0];
}

__global__ void k_scan2() {
    int run = 0;
    for (int b = 0; b < NBLK; b++) {
        int t = g_partial[b];
        g_partial[b] = run;
        run += t;
    }
    g_rowstart[NN] = run;
}

__global__ void k_scan3() {
    __shared__ int sm[1024];
    int tid = threadIdx.x;
    int i = blockIdx.x * 1024 + tid;
    int v = (i < NN) ? g_deg[i] : 0;
    sm[tid] = v;
    __syncthreads();
    for (int o = 1; o < 1024; o <<= 1) {
        int t = (tid >= o) ? sm[tid - o] : 0;
        __syncthreads();
        sm[tid] += t;
        __syncthreads();
    }
    int excl = sm[tid] - v + g_partial[blockIdx.x];
    if (i < NN) { g_rowstart[i] = excl; g_cursor[i] = excl; }
}

__global__ void k_fill(const int* __restrict__ src, const int* __restrict__ dst) {
    int e = blockIdx.x * blockDim.x + threadIdx.x;
    if (e >= EE) return;
    int d = dst[e], s = src[e];
    int p = atomicAdd(&g_cursor[d], 1);
    g_esrc[p] = s;
    g_ecoef[p] = g_dis[s] * g_dis[d];
}

// ---------------- GEMM layer 0: [N,9] @ [9,128] ----------------
__global__ __launch_bounds__(256) void k_gemm0(const float* __restrict__ x,
                                               const float* __restrict__ W0) {
    __shared__ float Ws[9 * 128];
    int tid = threadIdx.x;
    for (int i = tid; i < 9 * 128; i += 256) Ws[i] = W0[i];
    __syncthreads();
    int rsub = tid >> 5;       // 8 rows per block
    int c4 = tid & 31;         // 32 groups of 4 cols
    int row = blockIdx.x * 8 + rsub;
    if (row >= NN) return;
    float xr[9];
#pragma unroll
    for (int k = 0; k < 9; k++) xr[k] = __ldg(&x[row * 9 + k]);
    float4 acc = {0.f, 0.f, 0.f, 0.f};
#pragma unroll
    for (int k = 0; k < 9; k++) {
        float4 w = *(const float4*)&Ws[k * 128 + c4 * 4];
        acc.x += xr[k] * w.x;
        acc.y += xr[k] * w.y;
        acc.z += xr[k] * w.z;
        acc.w += xr[k] * w.w;
    }
    *(float4*)&g_h[row * 128 + c4 * 4] = acc;
}

// ---------------- GEMM layers 1,2: [N,128] @ [128,128] ----------------
// 128x128 tile per block, 256 threads, 8x8 microtile, K-strips of 16.
__global__ __launch_bounds__(256) void k_gemm128(const float* __restrict__ W) {
    __shared__ float Bs[16 * 128];
    __shared__ float As[128][17];
    int tid = threadIdx.x;
    int row0 = (tid >> 4) << 3;   // 0..120
    int col0 = (tid & 15) << 3;   // 0..120
    int rbase = blockIdx.x * 128;

    float acc[8][8];
#pragma unroll
    for (int i = 0; i < 8; i++)
#pragma unroll
        for (int j = 0; j < 8; j++) acc[i][j] = 0.f;

    int lr = tid >> 1;           // row this thread loads (0..127)
    int lk = (tid & 1) * 8;      // k offset (0 or 8)

    for (int kk = 0; kk < 128; kk += 16) {
        // load A strip [128 rows x 16 k]
        {
            int grow = rbase + lr;
            float4 v0 = {0.f, 0.f, 0.f, 0.f}, v1 = {0.f, 0.f, 0.f, 0.f};
            if (grow < NN) {
                const float* p = &g_act[(size_t)grow * 128 + kk + lk];
                v0 = *(const float4*)p;
                v1 = *(const float4*)(p + 4);
            }
            As[lr][lk + 0] = v0.x; As[lr][lk + 1] = v0.y;
            As[lr][lk + 2] = v0.z; As[lr][lk + 3] = v0.w;
            As[lr][lk + 4] = v1.x; As[lr][lk + 5] = v1.y;
            As[lr][lk + 6] = v1.z; As[lr][lk + 7] = v1.w;
        }
        // load B strip [16 k x 128 n] (contiguous slice of W)
        for (int i = tid; i < 16 * 128; i += 256) Bs[i] = W[kk * 128 + i];
        __syncthreads();
#pragma unroll
        for (int k = 0; k < 16; k++) {
            float a[8];
#pragma unroll
            for (int i = 0; i < 8; i++) a[i] = As[row0 + i][k];
            float4 b0 = *(const float4*)&Bs[k * 128 + col0];
            float4 b1 = *(const float4*)&Bs[k * 128 + col0 + 4];
            float b[8] = {b0.x, b0.y, b0.z, b0.w, b1.x, b1.y, b1.z, b1.w};
#pragma unroll
            for (int i = 0; i < 8; i++)
#pragma unroll
                for (int j = 0; j < 8; j++) acc[i][j] += a[i] * b[j];
        }
        __syncthreads();
    }
#pragma unroll
    for (int i = 0; i < 8; i++) {
        int grow = rbase + row0 + i;
        if (grow < NN) {
            float* p = &g_h[(size_t)grow * 128 + col0];
            *(float4*)(p + 0) = make_float4(acc[i][0], acc[i][1], acc[i][2], acc[i][3]);
            *(float4*)(p + 4) = make_float4(acc[i][4], acc[i][5], acc[i][6], acc[i][7]);
        }
    }
}

// ---------------- gather (CSR by dst): warp per node ----------------
__global__ __launch_bounds__(256) void k_gather(const float* __restrict__ bias) {
    int gwarp = (blockIdx.x * blockDim.x + threadIdx.x) >> 5;
    int lane = threadIdx.x & 31;
    if (gwarp >= NN) return;
    int i = gwarp;
    int beg = g_rowstart[i], end = g_rowstart[i + 1];
    const float4* hv = (const float4*)g_h;
    float4 acc = {0.f, 0.f, 0.f, 0.f};
    for (int e = beg; e < end; e++) {
        int s = g_esrc[e];
        float c = g_ecoef[e];
        float4 v = hv[(size_t)s * 32 + lane];
        acc.x += v.x * c; acc.y += v.y * c;
        acc.z += v.z * c; acc.w += v.w * c;
    }
    float di = g_dis[i];
    float d2 = di * di;
    float4 self = hv[(size_t)i * 32 + lane];
    float4 bb = ((const float4*)bias)[lane];
    acc.x += self.x * d2 + bb.x;
    acc.y += self.y * d2 + bb.y;
    acc.z += self.z * d2 + bb.z;
    acc.w += self.w * d2 + bb.w;
    ((float4*)g_agg)[(size_t)i * 32 + lane] = acc;
}

// ---------------- batch norm ----------------
__global__ void k_zstat() {
    int c = threadIdx.x;
    g_sum[c] = 0.f;
    g_sumsq[c] = 0.f;
}

__global__ __launch_bounds__(128) void k_bnstats() {
    int c = threadIdx.x;
    float s = 0.f, q = 0.f;
    for (int r = blockIdx.x; r < NN; r += gridDim.x) {
        float v = g_agg[(size_t)r * 128 + c];
        s += v;
        q += v * v;
    }
    atomicAdd(&g_sum[c], s);
    atomicAdd(&g_sumsq[c], q);
}

__global__ void k_bnfin(const float* __restrict__ gamma, const float* __restrict__ beta) {
    int c = threadIdx.x;
    float m = g_sum[c] * (1.0f / NN);
    float v = g_sumsq[c] * (1.0f / NN) - m * m;
    float inv = rsqrtf(v + 1e-5f);
    float sc = inv * gamma[c];
    g_scale[c] = sc;
    g_shift[c] = beta[c] - m * sc;
}

__global__ __launch_bounds__(256) void k_bnapply() {
    int idx = blockIdx.x * blockDim.x + threadIdx.x;  // over NN*32 float4 groups
    if (idx >= NN * 32) return;
    int c4 = idx & 31;
    float4 v = ((const float4*)g_agg)[idx];
    float4 sc = ((const float4*)g_scale)[c4];
    float4 sh = ((const float4*)g_shift)[c4];
    float4 o;
    o.x = fmaxf(v.x * sc.x + sh.x, 0.f);
    o.y = fmaxf(v.y * sc.y + sh.y, 0.f);
    o.z = fmaxf(v.z * sc.z + sh.z, 0.f);
    o.w = fmaxf(v.w * sc.w + sh.w, 0.f);
    ((float4*)g_act)[idx] = o;
}

// ---------------- pooling ----------------
__global__ void k_ranges(const int* __restrict__ batch) {
    int i = blockIdx.x * blockDim.x + threadIdx.x;
    if (i >= NN) return;
    int b = batch[i];
    if (i == 0 || batch[i - 1] != b) g_gstart[b] = i;
    if (i == NN - 1 || batch[i + 1] != b) g_gend[b] = i + 1;
}

__global__ __launch_bounds__(128) void k_pool() {
    int g = blockIdx.x;
    int c = threadIdx.x;
    int s = g_gstart[g], e = g_gend[g];
    float sum = 0.f, mx = -3.4e38f;
    for (int n = s; n < e; n++) {
        float v = g_act[(size_t)n * 128 + c];
        sum += v;
        mx = fmaxf(mx, v);
    }
    float cnt = (float)(e - s);
    g_z[g * 256 + c] = sum / cnt;
    g_z[g * 256 + 128 + c] = mx;
}

// ---------------- MLP head ----------------
__global__ __launch_bounds__(128) void k_mlp(const float* __restrict__ fc1_w,
                                             const float* __restrict__ fc1_b,
                                             const float* __restrict__ fc2_w,
                                             const float* __restrict__ fc2_b,
                                             const float* __restrict__ out_w,
                                             const float* __restrict__ out_b,
                                             float* __restrict__ out) {
    __shared__ float zs[256];
    __shared__ float h1[128];
    __shared__ float h2[64];
    int g = blockIdx.x;
    int t = threadIdx.x;
    zs[t] = g_z[g * 256 + t];
    zs[t + 128] = g_z[g * 256 + 128 + t];
    __syncthreads();
    float acc = fc1_b[t];
#pragma unroll 8
    for (int k = 0; k < 256; k++) acc += zs[k] * fc1_w[k * 128 + t];
    h1[t] = fmaxf(acc, 0.f);
    __syncthreads();
    if (t < 64) {
        float a = fc2_b[t];
#pragma unroll 8
        for (int k = 0; k < 128; k++) a += h1[k] * fc2_w[k * 64 + t];
        h2[t] = fmaxf(a, 0.f);
    }
    __syncthreads();
    if (t < 5) {
        float a = out_b[t];
#pragma unroll
        for (int k = 0; k < 64; k++) a += h2[k] * out_w[k * 5 + t];
        out[g * 5 + t] = a;
    }
}

// ---------------- launch ----------------
extern "C" void kernel_launch(void* const* d_in, const int* in_sizes, int n_in,
                              void* d_out, int out_size) {
    const float* x = (const float*)d_in[0];
    const int* ei = (const int*)d_in[1];
    const int* src = ei;
    const int* dst = ei + EE;
    const int* batch = (const int*)d_in[2];
    const float* W0 = (const float*)d_in[3];
    const float* b0 = (const float*)d_in[4];
    const float* gm0 = (const float*)d_in[5];
    const float* be0 = (const float*)d_in[6];
    const float* W1 = (const float*)d_in[7];
    const float* b1 = (const float*)d_in[8];
    const float* gm1 = (const float*)d_in[9];
    const float* be1 = (const float*)d_in[10];
    const float* W2 = (const float*)d_in[11];
    const float* b2 = (const float*)d_in[12];
    const float* gm2 = (const float*)d_in[13];
    const float* be2 = (const float*)d_in[14];
    const float* fc1_w = (const float*)d_in[15];
    const float* fc1_b = (const float*)d_in[16];
    const float* fc2_w = (const float*)d_in[17];
    const float* fc2_b = (const float*)d_in[18];
    const float* out_w = (const float*)d_in[19];
    const float* out_b = (const float*)d_in[20];
    float* out = (float*)d_out;

    // CSR build (shared by all 3 layers)
    k_zero_deg<<<(NN + 511) / 512, 512>>>();
    k_deg<<<(EE + 1023) / 1024, 1024>>>(dst);
    k_dis<<<(NN + 511) / 512, 512>>>();
    k_scan1<<<NBLK, 1024>>>();
    k_scan2<<<1, 1>>>();
    k_scan3<<<NBLK, 1024>>>();
    k_fill<<<(EE + 1023) / 1024, 1024>>>(src, dst);

    const float* Wl[3] = {W0, W1, W2};
    const float* bl[3] = {b0, b1, b2};
    const float* gl[3] = {gm0, gm1, gm2};
    const float* bel[3] = {be0, be1, be2};

    for (int l = 0; l < 3; l++) {
        if (l == 0)
            k_gemm0<<<(NN + 7) / 8, 256>>>(x, W0);
        else
            k_gemm128<<<(NN + 127) / 128, 256>>>(Wl[l]);
        k_gather<<<(NN * 32 + 255) / 256, 256>>>(bl[l]);
        k_zstat<<<1, 128>>>();
        k_bnstats<<<200, 128>>>();
        k_bnfin<<<1, 128>>>(gl[l], bel[l]);
        k_bnapply<<<(NN * 32 + 255) / 256, 256>>>();
    }

    k_ranges<<<(NN + 511) / 512, 512>>>(batch);
    k_pool<<<GG, 128>>>();
    k_mlp<<<GG, 128>>>(fc1_w, fc1_b, fc2_w, fc2_b, out_w, out_b, out);
}

// round 2
// speedup vs baseline: 1.6510x; 1.6510x over previous
#include <cuda_runtime.h>
#include <cuda_bf16.h>
#include <cstdint>

#define NN 50000
#define EE 600000
#define HH 128
#define GG 2048
#define NBLK2 196   // ceil(50000/256)

// ---------------- scratch (static device globals) ----------------
__device__ float g_h[NN * HH];      // GEMM output
__device__ float g_agg[NN * HH];    // conv output (pre-BN)
__device__ float g_dis[NN];         // deg^-1/2 (incl self loop)
__device__ int   g_deg[NN];
__device__ int   g_rowstart[NN + 1];
__device__ int   g_cursor[NN];
__device__ int2  g_edge[EE];        // (src, coef-bits) per CSR slot
__device__ int   g_partial[256];
__device__ int   g_poff[256];
__device__ float g_sumL[3][HH];
__device__ float g_sumsqL[3][HH];
__device__ int   g_gstart[GG], g_gend[GG];

// ---------------- init: zero deg + stats ----------------
__global__ void k_init() {
    int i = blockIdx.x * blockDim.x + threadIdx.x;
    if (i < NN) g_deg[i] = 0;
    if (i < 3 * HH) { ((float*)g_sumL)[i] = 0.f; ((float*)g_sumsqL)[i] = 0.f; }
    if (i == 0) g_rowstart[NN] = EE;
}

__global__ void k_deg(const int* __restrict__ dst) {
    int e = blockIdx.x * blockDim.x + threadIdx.x;
    if (e < EE) atomicAdd(&g_deg[dst[e]], 1);
}

// per-block degree sums (+ dis) via shuffles
__global__ __launch_bounds__(256) void k_blocksum() {
    int t = threadIdx.x;
    int i = blockIdx.x * 256 + t;
    int v = (i < NN) ? g_deg[i] : 0;
    if (i < NN) g_dis[i] = rsqrtf((float)v + 1.0f);
    int s = v;
#pragma unroll
    for (int o = 16; o > 0; o >>= 1) s += __shfl_down_sync(0xffffffffu, s, o);
    __shared__ int ws[8];
    if ((t & 31) == 0) ws[t >> 5] = s;
    __syncthreads();
    if (t < 8) {
        int x = ws[t];
#pragma unroll
        for (int o = 4; o > 0; o >>= 1) x += __shfl_down_sync(0xffu, x, o);
        if (t == 0) g_partial[blockIdx.x] = x;
    }
}

// single-block scan of 196 block sums -> exclusive offsets
__global__ void k_scanoff() {
    __shared__ int sm[256];
    int t = threadIdx.x;
    int v = (t < NBLK2) ? g_partial[t] : 0;
    sm[t] = v;
    __syncthreads();
    for (int o = 1; o < 256; o <<= 1) {
        int x = (t >= o) ? sm[t - o] : 0;
        __syncthreads();
        sm[t] += x;
        __syncthreads();
    }
    g_poff[t] = sm[t] - v;   // exclusive
}

// per-element exclusive scan within block + block offset
__global__ __launch_bounds__(256) void k_scanlocal() {
    int t = threadIdx.x;
    int lane = t & 31, w = t >> 5;
    int i = blockIdx.x * 256 + t;
    int v = (i < NN) ? g_deg[i] : 0;
    int x = v;
#pragma unroll
    for (int o = 1; o < 32; o <<= 1) {
        int y = __shfl_up_sync(0xffffffffu, x, o);
        if (lane >= o) x += y;
    }
    __shared__ int ws[8];
    if (lane == 31) ws[w] = x;
    __syncthreads();
    int add = g_poff[blockIdx.x];
    for (int j = 0; j < 8; j++) add += (j < w) ? ws[j] : 0;
    int excl = x - v + add;
    if (i < NN) { g_rowstart[i] = excl; g_cursor[i] = excl; }
}

__global__ void k_fill(const int* __restrict__ src, const int* __restrict__ dst) {
    int e = blockIdx.x * blockDim.x + threadIdx.x;
    if (e >= EE) return;
    int d = dst[e], s = src[e];
    int p = atomicAdd(&g_cursor[d], 1);
    float c = g_dis[s] * g_dis[d];
    g_edge[p] = make_int2(s, __float_as_int(c));
}

// ---------------- GEMM layer 0: [N,9] @ [9,128] ----------------
__global__ __launch_bounds__(256) void k_gemm0(const float* __restrict__ x,
                                               const float* __restrict__ W0) {
    __shared__ float Ws[9 * 128];
    int tid = threadIdx.x;
    for (int i = tid; i < 9 * 128; i += 256) Ws[i] = W0[i];
    __syncthreads();
    int rsub = tid >> 5;
    int c4 = tid & 31;
    int row = blockIdx.x * 8 + rsub;
    if (row >= NN) return;
    float xr[9];
#pragma unroll
    for (int k = 0; k < 9; k++) xr[k] = __ldg(&x[row * 9 + k]);
    float4 acc = {0.f, 0.f, 0.f, 0.f};
#pragma unroll
    for (int k = 0; k < 9; k++) {
        float4 w = *(const float4*)&Ws[k * 128 + c4 * 4];
        acc.x += xr[k] * w.x; acc.y += xr[k] * w.y;
        acc.z += xr[k] * w.z; acc.w += xr[k] * w.w;
    }
    *(float4*)&g_h[row * 128 + c4 * 4] = acc;
}

// ---------------- GEMM layers 1,2: relu(BN(g_agg)) @ W ----------------
// BN affine computed in-block from stats; applied on A-load.
__global__ __launch_bounds__(256) void k_gemm128(const float* __restrict__ W,
                                                 const float* __restrict__ gamma,
                                                 const float* __restrict__ beta,
                                                 int sidx) {
    __shared__ float sc[128], sh[128];
    __shared__ float Bs[16 * 128];
    __shared__ float As[128][17];
    int tid = threadIdx.x;
    if (tid < 128) {
        float m = g_sumL[sidx][tid] * (1.0f / NN);
        float v = g_sumsqL[sidx][tid] * (1.0f / NN) - m * m;
        float s = rsqrtf(v + 1e-5f) * gamma[tid];
        sc[tid] = s;
        sh[tid] = beta[tid] - m * s;
    }
    __syncthreads();

    int row0 = (tid >> 4) << 3;
    int col0 = (tid & 15) << 3;
    int rbase = blockIdx.x * 128;

    float acc[8][8];
#pragma unroll
    for (int i = 0; i < 8; i++)
#pragma unroll
        for (int j = 0; j < 8; j++) acc[i][j] = 0.f;

    int lr = tid >> 1;
    int lk = (tid & 1) * 8;

    for (int kk = 0; kk < 128; kk += 16) {
        {
            int grow = rbase + lr;
            float4 v0 = {0.f, 0.f, 0.f, 0.f}, v1 = {0.f, 0.f, 0.f, 0.f};
            if (grow < NN) {
                const float* p = &g_agg[(size_t)grow * 128 + kk + lk];
                v0 = *(const float4*)p;
                v1 = *(const float4*)(p + 4);
            }
            int kb = kk + lk;
            As[lr][lk + 0] = fmaxf(v0.x * sc[kb + 0] + sh[kb + 0], 0.f);
            As[lr][lk + 1] = fmaxf(v0.y * sc[kb + 1] + sh[kb + 1], 0.f);
            As[lr][lk + 2] = fmaxf(v0.z * sc[kb + 2] + sh[kb + 2], 0.f);
            As[lr][lk + 3] = fmaxf(v0.w * sc[kb + 3] + sh[kb + 3], 0.f);
            As[lr][lk + 4] = fmaxf(v1.x * sc[kb + 4] + sh[kb + 4], 0.f);
            As[lr][lk + 5] = fmaxf(v1.y * sc[kb + 5] + sh[kb + 5], 0.f);
            As[lr][lk + 6] = fmaxf(v1.z * sc[kb + 6] + sh[kb + 6], 0.f);
            As[lr][lk + 7] = fmaxf(v1.w * sc[kb + 7] + sh[kb + 7], 0.f);
        }
        for (int i = tid; i < 16 * 128; i += 256) Bs[i] = W[kk * 128 + i];
        __syncthreads();
#pragma unroll
        for (int k = 0; k < 16; k++) {
            float a[8];
#pragma unroll
            for (int i = 0; i < 8; i++) a[i] = As[row0 + i][k];
            float4 b0 = *(const float4*)&Bs[k * 128 + col0];
            float4 b1 = *(const float4*)&Bs[k * 128 + col0 + 4];
            float b[8] = {b0.x, b0.y, b0.z, b0.w, b1.x, b1.y, b1.z, b1.w};
#pragma unroll
            for (int i = 0; i < 8; i++)
#pragma unroll
                for (int j = 0; j < 8; j++) acc[i][j] += a[i] * b[j];
        }
        __syncthreads();
    }
#pragma unroll
    for (int i = 0; i < 8; i++) {
        int grow = rbase + row0 + i;
        if (grow < NN) {
            float* p = &g_h[(size_t)grow * 128 + col0];
            *(float4*)(p + 0) = make_float4(acc[i][0], acc[i][1], acc[i][2], acc[i][3]);
            *(float4*)(p + 4) = make_float4(acc[i][4], acc[i][5], acc[i][6], acc[i][7]);
        }
    }
}

// ---------------- gather + fused BN stats ----------------
// 8 warps/block = 8 nodes/block; grid = 6250 exactly (no tail).
__global__ __launch_bounds__(256) void k_gather(const float* __restrict__ bias, int sidx) {
    int w = threadIdx.x >> 5;
    int lane = threadIdx.x & 31;
    int node = blockIdx.x * 8 + w;
    int beg = g_rowstart[node], end = g_rowstart[node + 1];
    const float4* hv = (const float4*)g_h;

    float4 a0 = {0.f, 0.f, 0.f, 0.f}, a1 = {0.f, 0.f, 0.f, 0.f};
    int e = beg;
    for (; e + 2 <= end; e += 2) {
        int2 e0 = g_edge[e], e1 = g_edge[e + 1];
        float4 v0 = hv[(size_t)e0.x * 32 + lane];
        float4 v1 = hv[(size_t)e1.x * 32 + lane];
        float c0 = __int_as_float(e0.y), c1 = __int_as_float(e1.y);
        a0.x += v0.x * c0; a0.y += v0.y * c0; a0.z += v0.z * c0; a0.w += v0.w * c0;
        a1.x += v1.x * c1; a1.y += v1.y * c1; a1.z += v1.z * c1; a1.w += v1.w * c1;
    }
    if (e < end) {
        int2 e0 = g_edge[e];
        float4 v0 = hv[(size_t)e0.x * 32 + lane];
        float c0 = __int_as_float(e0.y);
        a0.x += v0.x * c0; a0.y += v0.y * c0; a0.z += v0.z * c0; a0.w += v0.w * c0;
    }
    float di = g_dis[node];
    float d2 = di * di;
    float4 self = hv[(size_t)node * 32 + lane];
    float4 bb = ((const float4*)bias)[lane];
    float4 acc;
    acc.x = a0.x + a1.x + self.x * d2 + bb.x;
    acc.y = a0.y + a1.y + self.y * d2 + bb.y;
    acc.z = a0.z + a1.z + self.z * d2 + bb.z;
    acc.w = a0.w + a1.w + self.w * d2 + bb.w;
    ((float4*)g_agg)[(size_t)node * 32 + lane] = acc;

    // fused BN stats: reduce 8 nodes in smem, then 128 spread atomics
    __shared__ float sm[8][128];
    *(float4*)&sm[w][lane * 4] = acc;
    __syncthreads();
    int t = threadIdx.x;
    if (t < 128) {
        float s = 0.f, q = 0.f;
#pragma unroll
        for (int j = 0; j < 8; j++) {
            float v = sm[j][t];
            s += v;
            q += v * v;
        }
        atomicAdd(&g_sumL[sidx][t], s);
        atomicAdd(&g_sumsqL[sidx][t], q);
    }
}

// ---------------- pooling boundaries ----------------
__global__ void k_ranges(const int* __restrict__ batch) {
    int i = blockIdx.x * blockDim.x + threadIdx.x;
    if (i >= NN) return;
    int b = batch[i];
    if (i == 0 || batch[i - 1] != b) g_gstart[b] = i;
    if (i == NN - 1 || batch[i + 1] != b) g_gend[b] = i + 1;
}

// ---------------- fused pool (BN2 inline) + MLP head ----------------
__global__ __launch_bounds__(128) void k_poolmlp(const float* __restrict__ gamma,
                                                 const float* __restrict__ beta,
                                                 const float* __restrict__ fc1_w,
                                                 const float* __restrict__ fc1_b,
                                                 const float* __restrict__ fc2_w,
                                                 const float* __restrict__ fc2_b,
                                                 const float* __restrict__ out_w,
                                                 const float* __restrict__ out_b,
                                                 float* __restrict__ out) {
    __shared__ float zs[256];
    __shared__ float h1[128];
    __shared__ float h2[64];
    int g = blockIdx.x;
    int t = threadIdx.x;

    // BN coefs for channel t (from layer-2 stats)
    float m = g_sumL[2][t] * (1.0f / NN);
    float va = g_sumsqL[2][t] * (1.0f / NN) - m * m;
    float sc = rsqrtf(va + 1e-5f) * gamma[t];
    float sh = beta[t] - m * sc;

    int s = g_gstart[g], e = g_gend[g];
    float sum = 0.f, mx = -3.4e38f;
    for (int n = s; n < e; n++) {
        float v = fmaxf(g_agg[(size_t)n * 128 + t] * sc + sh, 0.f);
        sum += v;
        mx = fmaxf(mx, v);
    }
    zs[t] = sum / (float)(e - s);
    zs[128 + t] = mx;
    __syncthreads();

    float acc = fc1_b[t];
#pragma unroll 8
    for (int k = 0; k < 256; k++) acc += zs[k] * fc1_w[k * 128 + t];
    h1[t] = fmaxf(acc, 0.f);
    __syncthreads();
    if (t < 64) {
        float a = fc2_b[t];
#pragma unroll 8
        for (int k = 0; k < 128; k++) a += h1[k] * fc2_w[k * 64 + t];
        h2[t] = fmaxf(a, 0.f);
    }
    __syncthreads();
    if (t < 5) {
        float a = out_b[t];
#pragma unroll
        for (int k = 0; k < 64; k++) a += h2[k] * out_w[k * 5 + t];
        out[g * 5 + t] = a;
    }
}

// ---------------- launch ----------------
extern "C" void kernel_launch(void* const* d_in, const int* in_sizes, int n_in,
                              void* d_out, int out_size) {
    const float* x = (const float*)d_in[0];
    const int* ei = (const int*)d_in[1];
    const int* src = ei;
    const int* dst = ei + EE;
    const int* batch = (const int*)d_in[2];
    const float* W0 = (const float*)d_in[3];
    const float* b0 = (const float*)d_in[4];
    const float* gm0 = (const float*)d_in[5];
    const float* be0 = (const float*)d_in[6];
    const float* W1 = (const float*)d_in[7];
    const float* b1 = (const float*)d_in[8];
    const float* gm1 = (const float*)d_in[9];
    const float* be1 = (const float*)d_in[10];
    const float* W2 = (const float*)d_in[11];
    const float* b2 = (const float*)d_in[12];
    const float* gm2 = (const float*)d_in[13];
    const float* be2 = (const float*)d_in[14];
    const float* fc1_w = (const float*)d_in[15];
    const float* fc1_b = (const float*)d_in[16];
    const float* fc2_w = (const float*)d_in[17];
    const float* fc2_b = (const float*)d_in[18];
    const float* out_w = (const float*)d_in[19];
    const float* out_b = (const float*)d_in[20];
    float* out = (float*)d_out;

    // CSR build
    k_init<<<(NN + 511) / 512, 512>>>();
    k_deg<<<(EE + 1023) / 1024, 1024>>>(dst);
    k_blocksum<<<NBLK2, 256>>>();
    k_scanoff<<<1, 256>>>();
    k_scanlocal<<<NBLK2, 256>>>();
    k_fill<<<(EE + 1023) / 1024, 1024>>>(src, dst);
    k_ranges<<<(NN + 511) / 512, 512>>>(batch);

    // layer 0
    k_gemm0<<<(NN + 7) / 8, 256>>>(x, W0);
    k_gather<<<NN / 8, 256>>>(b0, 0);
    // layer 1
    k_gemm128<<<(NN + 127) / 128, 256>>>(W1, gm0, be0, 0);
    k_gather<<<NN / 8, 256>>>(b1, 1);
    // layer 2
    k_gemm128<<<(NN + 127) / 128, 256>>>(W2, gm1, be1, 1);
    k_gather<<<NN / 8, 256>>>(b2, 2);

    // pool + head
    k_poolmlp<<<GG, 128>>>(gm2, be2, fc1_w, fc1_b, fc2_w, fc2_b,
                           out_w, out_b, out);
}

// round 4
// speedup vs baseline: 1.9881x; 1.2042x over previous
#include <cuda_runtime.h>
#include <cuda_bf16.h>
#include <cstdint>

#define NN 50000
#define EE 600000
#define HH 128
#define GG 2048
#define NBLK2 196        // ceil(50000/256)
#define MBLK 782         // ceil(50000/64)
#define KPAD 136         // padded row length (conflict-free fragment LDS)

// ---------------- scratch (static device globals) ----------------
__device__ float g_h[NN * HH];      // GEMM output
__device__ float g_agg[NN * HH];    // conv output (pre-BN)
__device__ float g_dis[NN];         // deg^-1/2 (incl self loop)
__device__ int   g_deg[NN];
__device__ int   g_rowstart[NN + 1];
__device__ int   g_cursor[NN];
__device__ int2  g_edge[EE];        // (src, coef-bits) per CSR slot
__device__ int   g_partial[256];
__device__ int   g_poff[256];
__device__ float g_sumL[3][HH];
__device__ float g_sumsqL[3][HH];
__device__ int   g_gstart[GG], g_gend[GG];
__device__ __nv_bfloat16 g_Wimg[2][2][128 * KPAD];  // [layer][hi/lo] W^T padded [n][k]

// ---------------- init: zero deg + stats ----------------
__global__ void k_init() {
    int i = blockIdx.x * blockDim.x + threadIdx.x;
    if (i < NN) g_deg[i] = 0;
    if (i < 3 * HH) { ((float*)g_sumL)[i] = 0.f; ((float*)g_sumsqL)[i] = 0.f; }
    if (i == 0) g_rowstart[NN] = EE;
}

// precompute bf16 hi/lo images of W1^T, W2^T:  img[n][k] = W[k][n], padded rows
__global__ void k_prepw(const float* __restrict__ W1, const float* __restrict__ W2) {
    int idx = blockIdx.x * blockDim.x + threadIdx.x;
    if (idx >= 2 * 128 * 128) return;
    int mat = idx >> 14;
    int rem = idx & 16383;
    int n = rem >> 7;
    int k = rem & 127;
    float v = (mat ? W2 : W1)[k * 128 + n];
    __nv_bfloat16 hi = __float2bfloat16(v);
    __nv_bfloat16 lo = __float2bfloat16(v - __bfloat162float(hi));
    g_Wimg[mat][0][n * KPAD + k] = hi;
    g_Wimg[mat][1][n * KPAD + k] = lo;
}

__global__ void k_deg(const int* __restrict__ dst) {
    int e = blockIdx.x * blockDim.x + threadIdx.x;
    if (e < EE) atomicAdd(&g_deg[dst[e]], 1);
}

__global__ __launch_bounds__(256) void k_blocksum() {
    int t = threadIdx.x;
    int i = blockIdx.x * 256 + t;
    int v = (i < NN) ? g_deg[i] : 0;
    if (i < NN) g_dis[i] = rsqrtf((float)v + 1.0f);
    int s = v;
#pragma unroll
    for (int o = 16; o > 0; o >>= 1) s += __shfl_down_sync(0xffffffffu, s, o);
    __shared__ int ws[8];
    if ((t & 31) == 0) ws[t >> 5] = s;
    __syncthreads();
    if (t < 8) {
        int x = ws[t];
#pragma unroll
        for (int o = 4; o > 0; o >>= 1) x += __shfl_down_sync(0xffu, x, o);
        if (t == 0) g_partial[blockIdx.x] = x;
    }
}

__global__ void k_scanoff() {
    __shared__ int sm[256];
    int t = threadIdx.x;
    int v = (t < NBLK2) ? g_partial[t] : 0;
    sm[t] = v;
    __syncthreads();
    for (int o = 1; o < 256; o <<= 1) {
        int x = (t >= o) ? sm[t - o] : 0;
        __syncthreads();
        sm[t] += x;
        __syncthreads();
    }
    g_poff[t] = sm[t] - v;
}

__global__ __launch_bounds__(256) void k_scanlocal() {
    int t = threadIdx.x;
    int lane = t & 31, w = t >> 5;
    int i = blockIdx.x * 256 + t;
    int v = (i < NN) ? g_deg[i] : 0;
    int x = v;
#pragma unroll
    for (int o = 1; o < 32; o <<= 1) {
        int y = __shfl_up_sync(0xffffffffu, x, o);
        if (lane >= o) x += y;
    }
    __shared__ int ws[8];
    if (lane == 31) ws[w] = x;
    __syncthreads();
    int add = g_poff[blockIdx.x];
    for (int j = 0; j < 8; j++) add += (j < w) ? ws[j] : 0;
    int excl = x - v + add;
    if (i < NN) { g_rowstart[i] = excl; g_cursor[i] = excl; }
}

__global__ void k_fill(const int* __restrict__ src, const int* __restrict__ dst) {
    int e = blockIdx.x * blockDim.x + threadIdx.x;
    if (e >= EE) return;
    int d = dst[e], s = src[e];
    int p = atomicAdd(&g_cursor[d], 1);
    float c = g_dis[s] * g_dis[d];
    g_edge[p] = make_int2(s, __float_as_int(c));
}

// ---------------- GEMM layer 0: [N,9] @ [9,128] (SIMT, tiny) ----------------
__global__ __launch_bounds__(256) void k_gemm0(const float* __restrict__ x,
                                               const float* __restrict__ W0) {
    __shared__ float Ws[9 * 128];
    int tid = threadIdx.x;
    for (int i = tid; i < 9 * 128; i += 256) Ws[i] = W0[i];
    __syncthreads();
    int rsub = tid >> 5;
    int c4 = tid & 31;
    int row = blockIdx.x * 8 + rsub;
    if (row >= NN) return;
    float xr[9];
#pragma unroll
    for (int k = 0; k < 9; k++) xr[k] = __ldg(&x[row * 9 + k]);
    float4 acc = {0.f, 0.f, 0.f, 0.f};
#pragma unroll
    for (int k = 0; k < 9; k++) {
        float4 w = *(const float4*)&Ws[k * 128 + c4 * 4];
        acc.x += xr[k] * w.x; acc.y += xr[k] * w.y;
        acc.z += xr[k] * w.z; acc.w += xr[k] * w.w;
    }
    *(float4*)&g_h[row * 128 + c4 * 4] = acc;
}

// ---------------- GEMM layers 1,2 via mma.sync bf16 split ----------------
// D = Ahi*Bhi + Ahi*Blo + Alo*Bhi, fp32 accumulate. A = relu(BN(g_agg)).
// Block: 64 rows x 128 cols, 8 warps (4 m-strips x 2 n-halves).
#define SM_SC  0
#define SM_SH  512
#define SM_AHI 1024
#define SM_ALO (1024 + 64 * KPAD * 2)
#define SM_BHI (1024 + 2 * 64 * KPAD * 2)
#define SM_BLO (SM_BHI + 128 * KPAD * 2)
#define SM_TOT (SM_BHI + 2 * 128 * KPAD * 2)

__global__ __launch_bounds__(256, 2)
void k_tcgemm(const float* __restrict__ gamma, const float* __restrict__ beta,
              int sidx, int wmat) {
    extern __shared__ char smem[];
    float* sc = (float*)(smem + SM_SC);
    float* sh = (float*)(smem + SM_SH);
    __nv_bfloat16* Ahi = (__nv_bfloat16*)(smem + SM_AHI);
    __nv_bfloat16* Alo = (__nv_bfloat16*)(smem + SM_ALO);
    __nv_bfloat16* Bhi = (__nv_bfloat16*)(smem + SM_BHI);
    __nv_bfloat16* Blo = (__nv_bfloat16*)(smem + SM_BLO);

    int tid = threadIdx.x;
    int rbase = blockIdx.x * 64;

    // BN affine from accumulated stats
    if (tid < 128) {
        float m = g_sumL[sidx][tid] * (1.0f / NN);
        float v = g_sumsqL[sidx][tid] * (1.0f / NN) - m * m;
        float s = rsqrtf(v + 1e-5f) * gamma[tid];
        sc[tid] = s;
        sh[tid] = beta[tid] - m * s;
    }

    // copy W images into smem (128 rows x KPAD, only first 128 cols meaningful)
    {
        const float4* hsrc = (const float4*)g_Wimg[wmat][0];
        const float4* lsrc = (const float4*)g_Wimg[wmat][1];
        float4* hd = (float4*)Bhi;
        float4* ld = (float4*)Blo;
        for (int i = tid; i < 128 * KPAD / 8; i += 256) { hd[i] = hsrc[i]; ld[i] = lsrc[i]; }
    }
    __syncthreads();   // sc/sh ready before A conversion

    // A tile: BN+ReLU+split to bf16 hi/lo
#pragma unroll
    for (int it = 0; it < 8; it++) {
        int g = tid + it * 256;        // 0..2047 float4 groups (64 rows x 32)
        int row = g >> 5;
        int c = (g & 31) * 4;
        int grow = rbase + row;
        float4 v = {0.f, 0.f, 0.f, 0.f};
        if (grow < NN) v = *(const float4*)&g_agg[(size_t)grow * 128 + c];
        float a0 = fmaxf(v.x * sc[c + 0] + sh[c + 0], 0.f);
        float a1 = fmaxf(v.y * sc[c + 1] + sh[c + 1], 0.f);
        float a2 = fmaxf(v.z * sc[c + 2] + sh[c + 2], 0.f);
        float a3 = fmaxf(v.w * sc[c + 3] + sh[c + 3], 0.f);
        __nv_bfloat16 h0 = __float2bfloat16(a0), h1 = __float2bfloat16(a1);
        __nv_bfloat16 h2 = __float2bfloat16(a2), h3 = __float2bfloat16(a3);
        int base = row * KPAD + c;
        Ahi[base + 0] = h0; Ahi[base + 1] = h1; Ahi[base + 2] = h2; Ahi[base + 3] = h3;
        Alo[base + 0] = __float2bfloat16(a0 - __bfloat162float(h0));
        Alo[base + 1] = __float2bfloat16(a1 - __bfloat162float(h1));
        Alo[base + 2] = __float2bfloat16(a2 - __bfloat162float(h2));
        Alo[base + 3] = __float2bfloat16(a3 - __bfloat162float(h3));
    }
    __syncthreads();

    int wid = tid >> 5;
    int lane = tid & 31;
    int wm = wid & 3;          // m strip (16 rows)
    int wn = wid >> 2;         // n half (64 cols)
    int grp = lane >> 2;       // 0..7
    int tig = lane & 3;        // 0..3

    float acc[8][4];
#pragma unroll
    for (int i = 0; i < 8; i++)
#pragma unroll
        for (int j = 0; j < 4; j++) acc[i][j] = 0.f;

    const __nv_bfloat16* Apass[3] = {Ahi, Ahi, Alo};
    const __nv_bfloat16* Bpass[3] = {Bhi, Blo, Bhi};

#pragma unroll
    for (int p = 0; p < 3; p++) {
        const __nv_bfloat16* A = Apass[p];
        const __nv_bfloat16* B = Bpass[p];
#pragma unroll
        for (int kk = 0; kk < 8; kk++) {
            int k = kk * 16;
            int ra = (wm * 16 + grp) * KPAD;
            uint32_t a0 = *(const uint32_t*)&A[ra + k + 2 * tig];
            uint32_t a1 = *(const uint32_t*)&A[ra + 8 * KPAD + k + 2 * tig];
            uint32_t a2 = *(const uint32_t*)&A[ra + k + 8 + 2 * tig];
            uint32_t a3 = *(const uint32_t*)&A[ra + 8 * KPAD + k + 8 + 2 * tig];
#pragma unroll
            for (int nt = 0; nt < 8; nt++) {
                int n0 = wn * 64 + nt * 8 + grp;
                uint32_t b0 = *(const uint32_t*)&B[n0 * KPAD + k + 2 * tig];
                uint32_t b1 = *(const uint32_t*)&B[n0 * KPAD + k + 8 + 2 * tig];
                asm volatile(
                    "mma.sync.aligned.m16n8k16.row.col.f32.bf16.bf16.f32 "
                    "{%0,%1,%2,%3}, {%4,%5,%6,%7}, {%8,%9}, {%0,%1,%2,%3};"
                    : "+f"(acc[nt][0]), "+f"(acc[nt][1]), "+f"(acc[nt][2]), "+f"(acc[nt][3])
                    : "r"(a0), "r"(a1), "r"(a2), "r"(a3), "r"(b0), "r"(b1));
            }
        }
    }

    // epilogue: write fp32 g_h
    int row0 = rbase + wm * 16 + grp;
    int row1 = row0 + 8;
#pragma unroll
    for (int nt = 0; nt < 8; nt++) {
        int col = wn * 64 + nt * 8 + tig * 2;
        if (row0 < NN)
            *(float2*)&g_h[(size_t)row0 * 128 + col] = make_float2(acc[nt][0], acc[nt][1]);
        if (row1 < NN)
            *(float2*)&g_h[(size_t)row1 * 128 + col] = make_float2(acc[nt][2], acc[nt][3]);
    }
}

// ---------------- gather + fused BN stats ----------------
__global__ __launch_bounds__(256) void k_gather(const float* __restrict__ bias, int sidx) {
    int w = threadIdx.x >> 5;
    int lane = threadIdx.x & 31;
    int node = blockIdx.x * 8 + w;
    int beg = g_rowstart[node], end = g_rowstart[node + 1];
    const float4* hv = (const float4*)g_h;

    float4 a0 = {0.f, 0.f, 0.f, 0.f}, a1 = {0.f, 0.f, 0.f, 0.f};
    int e = beg;
    for (; e + 2 <= end; e += 2) {
        int2 e0 = g_edge[e], e1 = g_edge[e + 1];
        float4 v0 = hv[(size_t)e0.x * 32 + lane];
        float4 v1 = hv[(size_t)e1.x * 32 + lane];
        float c0 = __int_as_float(e0.y), c1 = __int_as_float(e1.y);
        a0.x += v0.x * c0; a0.y += v0.y * c0; a0.z += v0.z * c0; a0.w += v0.w * c0;
        a1.x += v1.x * c1; a1.y += v1.y * c1; a1.z += v1.z * c1; a1.w += v1.w * c1;
    }
    if (e < end) {
        int2 e0 = g_edge[e];
        float4 v0 = hv[(size_t)e0.x * 32 + lane];
        float c0 = __int_as_float(e0.y);
        a0.x += v0.x * c0; a0.y += v0.y * c0; a0.z += v0.z * c0; a0.w += v0.w * c0;
    }
    float di = g_dis[node];
    float d2 = di * di;
    float4 self = hv[(size_t)node * 32 + lane];
    float4 bb = ((const float4*)bias)[lane];
    float4 acc;
    acc.x = a0.x + a1.x + self.x * d2 + bb.x;
    acc.y = a0.y + a1.y + self.y * d2 + bb.y;
    acc.z = a0.z + a1.z + self.z * d2 + bb.z;
    acc.w = a0.w + a1.w + self.w * d2 + bb.w;
    ((float4*)g_agg)[(size_t)node * 32 + lane] = acc;

    __shared__ float sm[8][128];
    *(float4*)&sm[w][lane * 4] = acc;
    __syncthreads();
    int t = threadIdx.x;
    if (t < 128) {
        float s = 0.f, q = 0.f;
#pragma unroll
        for (int j = 0; j < 8; j++) {
            float v = sm[j][t];
            s += v;
            q += v * v;
        }
        atomicAdd(&g_sumL[sidx][t], s);
        atomicAdd(&g_sumsqL[sidx][t], q);
    }
}

// ---------------- pooling boundaries ----------------
__global__ void k_ranges(const int* __restrict__ batch) {
    int i = blockIdx.x * blockDim.x + threadIdx.x;
    if (i >= NN) return;
    int b = batch[i];
    if (i == 0 || batch[i - 1] != b) g_gstart[b] = i;
    if (i == NN - 1 || batch[i + 1] != b) g_gend[b] = i + 1;
}

// ---------------- fused pool (BN2 inline) + MLP head ----------------
__global__ __launch_bounds__(128) void k_poolmlp(const float* __restrict__ gamma,
                                                 const float* __restrict__ beta,
                                                 const float* __restrict__ fc1_w,
                                                 const float* __restrict__ fc1_b,
                                                 const float* __restrict__ fc2_w,
                                                 const float* __restrict__ fc2_b,
                                                 const float* __restrict__ out_w,
                                                 const float* __restrict__ out_b,
                                                 float* __restrict__ out) {
    __shared__ float zs[256];
    __shared__ float h1[128];
    __shared__ float h2[64];
    int g = blockIdx.x;
    int t = threadIdx.x;

    float m = g_sumL[2][t] * (1.0f / NN);
    float va = g_sumsqL[2][t] * (1.0f / NN) - m * m;
    float sc = rsqrtf(va + 1e-5f) * gamma[t];
    float sh = beta[t] - m * sc;

    int s = g_gstart[g], e = g_gend[g];
    float sum = 0.f, mx = -3.4e38f;
    for (int n = s; n < e; n++) {
        float v = fmaxf(g_agg[(size_t)n * 128 + t] * sc + sh, 0.f);
        sum += v;
        mx = fmaxf(mx, v);
    }
    zs[t] = sum / (float)(e - s);
    zs[128 + t] = mx;
    __syncthreads();

    float acc = fc1_b[t];
#pragma unroll 8
    for (int k = 0; k < 256; k++) acc += zs[k] * fc1_w[k * 128 + t];
    h1[t] = fmaxf(acc, 0.f);
    __syncthreads();
    if (t < 64) {
        float a = fc2_b[t];
#pragma unroll 8
        for (int k = 0; k < 128; k++) a += h1[k] * fc2_w[k * 64 + t];
        h2[t] = fmaxf(a, 0.f);
    }
    __syncthreads();
    if (t < 5) {
        float a = out_b[t];
#pragma unroll
        for (int k = 0; k < 64; k++) a += h2[k] * out_w[k * 5 + t];
        out[g * 5 + t] = a;
    }
}

// ---------------- launch ----------------
extern "C" void kernel_launch(void* const* d_in, const int* in_sizes, int n_in,
                              void* d_out, int out_size) {
    const float* x = (const float*)d_in[0];
    const int* ei = (const int*)d_in[1];
    const int* src = ei;
    const int* dst = ei + EE;
    const int* batch = (const int*)d_in[2];
    const float* W0 = (const float*)d_in[3];
    const float* b0 = (const float*)d_in[4];
    const float* gm0 = (const float*)d_in[5];
    const float* be0 = (const float*)d_in[6];
    const float* W1 = (const float*)d_in[7];
    const float* b1 = (const float*)d_in[8];
    const float* gm1 = (const float*)d_in[9];
    const float* be1 = (const float*)d_in[10];
    const float* W2 = (const float*)d_in[11];
    const float* b2 = (const float*)d_in[12];
    const float* gm2 = (const float*)d_in[13];
    const float* be2 = (const float*)d_in[14];
    const float* fc1_w = (const float*)d_in[15];
    const float* fc1_b = (const float*)d_in[16];
    const float* fc2_w = (const float*)d_in[17];
    const float* fc2_b = (const float*)d_in[18];
    const float* out_w = (const float*)d_in[19];
    const float* out_b = (const float*)d_in[20];
    float* out = (float*)d_out;

    cudaFuncSetAttribute(k_tcgemm, cudaFuncAttributeMaxDynamicSharedMemorySize, SM_TOT);

    // CSR build + weight image prep
    k_init<<<(NN + 511) / 512, 512>>>();
    k_prepw<<<128, 256>>>(W1, W2);
    k_deg<<<(EE + 1023) / 1024, 1024>>>(dst);
    k_blocksum<<<NBLK2, 256>>>();
    k_scanoff<<<1, 256>>>();
    k_scanlocal<<<NBLK2, 256>>>();
    k_fill<<<(EE + 1023) / 1024, 1024>>>(src, dst);
    k_ranges<<<(NN + 511) / 512, 512>>>(batch);

    // layer 0
    k_gemm0<<<(NN + 7) / 8, 256>>>(x, W0);
    k_gather<<<NN / 8, 256>>>(b0, 0);
    // layer 1
    k_tcgemm<<<MBLK, 256, SM_TOT>>>(gm0, be0, 0, 0);
    k_gather<<<NN / 8, 256>>>(b1, 1);
    // layer 2
    k_tcgemm<<<MBLK, 256, SM_TOT>>>(gm1, be1, 1, 1);
    k_gather<<<NN / 8, 256>>>(b2, 2);

    // pool + head
    k_poolmlp<<<GG, 128>>>(gm2, be2, fc1_w, fc1_b, fc2_w, fc2_b,
                           out_w, out_b, out);
}

// round 5
// speedup vs baseline: 2.0918x; 1.0521x over previous
#include <cuda_runtime.h>
#include <cuda_bf16.h>
#include <cuda_fp16.h>
#include <cstdint>

#define NN 50000
#define EE 600000
#define HH 128
#define GG 2048
#define NBLK2 196        // ceil(50000/256)
#define MBLK 782         // ceil(50000/64)
#define KPAD 136         // padded row length (conflict-free fragment LDS)

// ---------------- scratch (static device globals) ----------------
__device__ __half g_h16[NN * HH];   // GEMM output (fp16, gather operand)
__device__ float g_agg[NN * HH];    // conv output (pre-BN, fp32)
__device__ float g_dis[NN];         // deg^-1/2 (incl self loop)
__device__ int   g_deg[NN];
__device__ int   g_rowstart[NN + 1];
__device__ int   g_cursor[NN];
__device__ int2  g_edge[EE];        // (src, coef-bits) per CSR slot
__device__ int   g_partial[256];
__device__ int   g_poff[256];
__device__ float g_sumL[3][HH];
__device__ float g_sumsqL[3][HH];
__device__ int   g_gstart[GG], g_gend[GG];
__device__ __nv_bfloat16 g_Wimg[2][2][128 * KPAD];  // [layer][hi/lo] W^T padded [n][k]

// ---------------- init: zero deg + stats ----------------
__global__ void k_init() {
    int i = blockIdx.x * blockDim.x + threadIdx.x;
    if (i < NN) g_deg[i] = 0;
    if (i < 3 * HH) { ((float*)g_sumL)[i] = 0.f; ((float*)g_sumsqL)[i] = 0.f; }
    if (i == 0) g_rowstart[NN] = EE;
}

// precompute bf16 hi/lo images of W1^T, W2^T:  img[n][k] = W[k][n], padded rows
__global__ void k_prepw(const float* __restrict__ W1, const float* __restrict__ W2) {
    int idx = blockIdx.x * blockDim.x + threadIdx.x;
    if (idx >= 2 * 128 * 128) return;
    int mat = idx >> 14;
    int rem = idx & 16383;
    int n = rem >> 7;
    int k = rem & 127;
    float v = (mat ? W2 : W1)[k * 128 + n];
    __nv_bfloat16 hi = __float2bfloat16(v);
    __nv_bfloat16 lo = __float2bfloat16(v - __bfloat162float(hi));
    g_Wimg[mat][0][n * KPAD + k] = hi;
    g_Wimg[mat][1][n * KPAD + k] = lo;
}

__global__ void k_deg(const int* __restrict__ dst) {
    int e = blockIdx.x * blockDim.x + threadIdx.x;
    if (e < EE) atomicAdd(&g_deg[dst[e]], 1);
}

__global__ __launch_bounds__(256) void k_blocksum() {
    int t = threadIdx.x;
    int i = blockIdx.x * 256 + t;
    int v = (i < NN) ? g_deg[i] : 0;
    if (i < NN) g_dis[i] = rsqrtf((float)v + 1.0f);
    int s = v;
#pragma unroll
    for (int o = 16; o > 0; o >>= 1) s += __shfl_down_sync(0xffffffffu, s, o);
    __shared__ int ws[8];
    if ((t & 31) == 0) ws[t >> 5] = s;
    __syncthreads();
    if (t < 8) {
        int x = ws[t];
#pragma unroll
        for (int o = 4; o > 0; o >>= 1) x += __shfl_down_sync(0xffu, x, o);
        if (t == 0) g_partial[blockIdx.x] = x;
    }
}

__global__ void k_scanoff() {
    __shared__ int sm[256];
    int t = threadIdx.x;
    int v = (t < NBLK2) ? g_partial[t] : 0;
    sm[t] = v;
    __syncthreads();
    for (int o = 1; o < 256; o <<= 1) {
        int x = (t >= o) ? sm[t - o] : 0;
        __syncthreads();
        sm[t] += x;
        __syncthreads();
    }
    g_poff[t] = sm[t] - v;
}

__global__ __launch_bounds__(256) void k_scanlocal() {
    int t = threadIdx.x;
    int lane = t & 31, w = t >> 5;
    int i = blockIdx.x * 256 + t;
    int v = (i < NN) ? g_deg[i] : 0;
    int x = v;
#pragma unroll
    for (int o = 1; o < 32; o <<= 1) {
        int y = __shfl_up_sync(0xffffffffu, x, o);
        if (lane >= o) x += y;
    }
    __shared__ int ws[8];
    if (lane == 31) ws[w] = x;
    __syncthreads();
    int add = g_poff[blockIdx.x];
    for (int j = 0; j < 8; j++) add += (j < w) ? ws[j] : 0;
    int excl = x - v + add;
    if (i < NN) { g_rowstart[i] = excl; g_cursor[i] = excl; }
}

__global__ void k_fill(const int* __restrict__ src, const int* __restrict__ dst) {
    int e = blockIdx.x * blockDim.x + threadIdx.x;
    if (e >= EE) return;
    int d = dst[e], s = src[e];
    int p = atomicAdd(&g_cursor[d], 1);
    float c = g_dis[s] * g_dis[d];
    g_edge[p] = make_int2(s, __float_as_int(c));
}

// ---------------- GEMM layer 0: [N,9] @ [9,128] (SIMT, tiny) ----------------
__global__ __launch_bounds__(256) void k_gemm0(const float* __restrict__ x,
                                               const float* __restrict__ W0) {
    __shared__ float Ws[9 * 128];
    int tid = threadIdx.x;
    for (int i = tid; i < 9 * 128; i += 256) Ws[i] = W0[i];
    __syncthreads();
    int rsub = tid >> 5;
    int c4 = tid & 31;
    int row = blockIdx.x * 8 + rsub;
    if (row >= NN) return;
    float xr[9];
#pragma unroll
    for (int k = 0; k < 9; k++) xr[k] = __ldg(&x[row * 9 + k]);
    float4 acc = {0.f, 0.f, 0.f, 0.f};
#pragma unroll
    for (int k = 0; k < 9; k++) {
        float4 w = *(const float4*)&Ws[k * 128 + c4 * 4];
        acc.x += xr[k] * w.x; acc.y += xr[k] * w.y;
        acc.z += xr[k] * w.z; acc.w += xr[k] * w.w;
    }
    __half2 p0 = __floats2half2_rn(acc.x, acc.y);
    __half2 p1 = __floats2half2_rn(acc.z, acc.w);
    uint2 u;
    u.x = *(uint32_t*)&p0;
    u.y = *(uint32_t*)&p1;
    ((uint2*)g_h16)[row * 32 + c4] = u;
}

// ---------------- GEMM layers 1,2 via mma.sync bf16 split ----------------
// D = Ahi*Bhi + Ahi*Blo + Alo*Bhi, fp32 accumulate. A = relu(BN(g_agg)).
// Block: 64 rows x 128 cols, 8 warps (4 m-strips x 2 n-halves).
#define SM_SC  0
#define SM_SH  512
#define SM_AHI 1024
#define SM_ALO (1024 + 64 * KPAD * 2)
#define SM_BHI (1024 + 2 * 64 * KPAD * 2)
#define SM_BLO (SM_BHI + 128 * KPAD * 2)
#define SM_TOT (SM_BHI + 2 * 128 * KPAD * 2)

__global__ __launch_bounds__(256, 2)
void k_tcgemm(const float* __restrict__ gamma, const float* __restrict__ beta,
              int sidx, int wmat) {
    extern __shared__ char smem[];
    float* sc = (float*)(smem + SM_SC);
    float* sh = (float*)(smem + SM_SH);
    __nv_bfloat16* Ahi = (__nv_bfloat16*)(smem + SM_AHI);
    __nv_bfloat16* Alo = (__nv_bfloat16*)(smem + SM_ALO);
    __nv_bfloat16* Bhi = (__nv_bfloat16*)(smem + SM_BHI);
    __nv_bfloat16* Blo = (__nv_bfloat16*)(smem + SM_BLO);

    int tid = threadIdx.x;
    int rbase = blockIdx.x * 64;

    // BN affine from accumulated stats
    if (tid < 128) {
        float m = g_sumL[sidx][tid] * (1.0f / NN);
        float v = g_sumsqL[sidx][tid] * (1.0f / NN) - m * m;
        float s = rsqrtf(v + 1e-5f) * gamma[tid];
        sc[tid] = s;
        sh[tid] = beta[tid] - m * s;
    }

    // copy W images into smem
    {
        const float4* hsrc = (const float4*)g_Wimg[wmat][0];
        const float4* lsrc = (const float4*)g_Wimg[wmat][1];
        float4* hd = (float4*)Bhi;
        float4* ld = (float4*)Blo;
        for (int i = tid; i < 128 * KPAD / 8; i += 256) { hd[i] = hsrc[i]; ld[i] = lsrc[i]; }
    }
    __syncthreads();   // sc/sh ready before A conversion

    // A tile: BN+ReLU+split to bf16 hi/lo
#pragma unroll
    for (int it = 0; it < 8; it++) {
        int g = tid + it * 256;        // 0..2047 float4 groups (64 rows x 32)
        int row = g >> 5;
        int c = (g & 31) * 4;
        int grow = rbase + row;
        float4 v = {0.f, 0.f, 0.f, 0.f};
        if (grow < NN) v = *(const float4*)&g_agg[(size_t)grow * 128 + c];
        float a0 = fmaxf(v.x * sc[c + 0] + sh[c + 0], 0.f);
        float a1 = fmaxf(v.y * sc[c + 1] + sh[c + 1], 0.f);
        float a2 = fmaxf(v.z * sc[c + 2] + sh[c + 2], 0.f);
        float a3 = fmaxf(v.w * sc[c + 3] + sh[c + 3], 0.f);
        __nv_bfloat16 h0 = __float2bfloat16(a0), h1 = __float2bfloat16(a1);
        __nv_bfloat16 h2 = __float2bfloat16(a2), h3 = __float2bfloat16(a3);
        int base = row * KPAD + c;
        Ahi[base + 0] = h0; Ahi[base + 1] = h1; Ahi[base + 2] = h2; Ahi[base + 3] = h3;
        Alo[base + 0] = __float2bfloat16(a0 - __bfloat162float(h0));
        Alo[base + 1] = __float2bfloat16(a1 - __bfloat162float(h1));
        Alo[base + 2] = __float2bfloat16(a2 - __bfloat162float(h2));
        Alo[base + 3] = __float2bfloat16(a3 - __bfloat162float(h3));
    }
    __syncthreads();

    int wid = tid >> 5;
    int lane = tid & 31;
    int wm = wid & 3;          // m strip (16 rows)
    int wn = wid >> 2;         // n half (64 cols)
    int grp = lane >> 2;       // 0..7
    int tig = lane & 3;        // 0..3

    float acc[8][4];
#pragma unroll
    for (int i = 0; i < 8; i++)
#pragma unroll
        for (int j = 0; j < 4; j++) acc[i][j] = 0.f;

    const __nv_bfloat16* Apass[3] = {Ahi, Ahi, Alo};
    const __nv_bfloat16* Bpass[3] = {Bhi, Blo, Bhi};

#pragma unroll
    for (int p = 0; p < 3; p++) {
        const __nv_bfloat16* A = Apass[p];
        const __nv_bfloat16* B = Bpass[p];
#pragma unroll
        for (int kk = 0; kk < 8; kk++) {
            int k = kk * 16;
            int ra = (wm * 16 + grp) * KPAD;
            uint32_t a0 = *(const uint32_t*)&A[ra + k + 2 * tig];
            uint32_t a1 = *(const uint32_t*)&A[ra + 8 * KPAD + k + 2 * tig];
            uint32_t a2 = *(const uint32_t*)&A[ra + k + 8 + 2 * tig];
            uint32_t a3 = *(const uint32_t*)&A[ra + 8 * KPAD + k + 8 + 2 * tig];
#pragma unroll
            for (int nt = 0; nt < 8; nt++) {
                int n0 = wn * 64 + nt * 8 + grp;
                uint32_t b0 = *(const uint32_t*)&B[n0 * KPAD + k + 2 * tig];
                uint32_t b1 = *(const uint32_t*)&B[n0 * KPAD + k + 8 + 2 * tig];
                asm volatile(
                    "mma.sync.aligned.m16n8k16.row.col.f32.bf16.bf16.f32 "
                    "{%0,%1,%2,%3}, {%4,%5,%6,%7}, {%8,%9}, {%0,%1,%2,%3};"
                    : "+f"(acc[nt][0]), "+f"(acc[nt][1]), "+f"(acc[nt][2]), "+f"(acc[nt][3])
                    : "r"(a0), "r"(a1), "r"(a2), "r"(a3), "r"(b0), "r"(b1));
            }
        }
    }

    // epilogue: write fp16 g_h16
    int row0 = rbase + wm * 16 + grp;
    int row1 = row0 + 8;
    __half2* hv = (__half2*)g_h16;
#pragma unroll
    for (int nt = 0; nt < 8; nt++) {
        int col = wn * 64 + nt * 8 + tig * 2;
        if (row0 < NN)
            hv[row0 * 64 + (col >> 1)] = __floats2half2_rn(acc[nt][0], acc[nt][1]);
        if (row1 < NN)
            hv[row1 * 64 + (col >> 1)] = __floats2half2_rn(acc[nt][2], acc[nt][3]);
    }
}

// ---------------- gather (fp16 operand) + fused BN stats ----------------
__global__ __launch_bounds__(256) void k_gather(const float* __restrict__ bias, int sidx) {
    int w = threadIdx.x >> 5;
    int lane = threadIdx.x & 31;
    int node = blockIdx.x * 8 + w;
    int beg = g_rowstart[node], end = g_rowstart[node + 1];
    const uint2* hv = (const uint2*)g_h16;  // 4 halves per uint2; 32 lanes = 128 ch

    float4 a0 = {0.f, 0.f, 0.f, 0.f}, a1 = {0.f, 0.f, 0.f, 0.f};
    int e = beg;
    for (; e + 2 <= end; e += 2) {
        int2 e0 = g_edge[e], e1 = g_edge[e + 1];
        uint2 u0 = hv[(size_t)e0.x * 32 + lane];
        uint2 u1 = hv[(size_t)e1.x * 32 + lane];
        float c0 = __int_as_float(e0.y), c1 = __int_as_float(e1.y);
        float2 f00 = __half22float2(*(__half2*)&u0.x);
        float2 f01 = __half22float2(*(__half2*)&u0.y);
        float2 f10 = __half22float2(*(__half2*)&u1.x);
        float2 f11 = __half22float2(*(__half2*)&u1.y);
        a0.x += f00.x * c0; a0.y += f00.y * c0; a0.z += f01.x * c0; a0.w += f01.y * c0;
        a1.x += f10.x * c1; a1.y += f10.y * c1; a1.z += f11.x * c1; a1.w += f11.y * c1;
    }
    if (e < end) {
        int2 e0 = g_edge[e];
        uint2 u0 = hv[(size_t)e0.x * 32 + lane];
        float c0 = __int_as_float(e0.y);
        float2 f00 = __half22float2(*(__half2*)&u0.x);
        float2 f01 = __half22float2(*(__half2*)&u0.y);
        a0.x += f00.x * c0; a0.y += f00.y * c0; a0.z += f01.x * c0; a0.w += f01.y * c0;
    }
    float di = g_dis[node];
    float d2 = di * di;
    uint2 us = hv[(size_t)node * 32 + lane];
    float2 s0 = __half22float2(*(__half2*)&us.x);
    float2 s1 = __half22float2(*(__half2*)&us.y);
    float4 bb = ((const float4*)bias)[lane];
    float4 acc;
    acc.x = a0.x + a1.x + s0.x * d2 + bb.x;
    acc.y = a0.y + a1.y + s0.y * d2 + bb.y;
    acc.z = a0.z + a1.z + s1.x * d2 + bb.z;
    acc.w = a0.w + a1.w + s1.y * d2 + bb.w;
    ((float4*)g_agg)[(size_t)node * 32 + lane] = acc;

    __shared__ float sm[8][128];
    *(float4*)&sm[w][lane * 4] = acc;
    __syncthreads();
    int t = threadIdx.x;
    if (t < 128) {
        float s = 0.f, q = 0.f;
#pragma unroll
        for (int j = 0; j < 8; j++) {
            float v = sm[j][t];
            s += v;
            q += v * v;
        }
        atomicAdd(&g_sumL[sidx][t], s);
        atomicAdd(&g_sumsqL[sidx][t], q);
    }
}

// ---------------- pooling boundaries ----------------
__global__ void k_ranges(const int* __restrict__ batch) {
    int i = blockIdx.x * blockDim.x + threadIdx.x;
    if (i >= NN) return;
    int b = batch[i];
    if (i == 0 || batch[i - 1] != b) g_gstart[b] = i;
    if (i == NN - 1 || batch[i + 1] != b) g_gend[b] = i + 1;
}

// ---------------- fused pool (BN2 inline) + MLP head ----------------
__global__ __launch_bounds__(128) void k_poolmlp(const float* __restrict__ gamma,
                                                 const float* __restrict__ beta,
                                                 const float* __restrict__ fc1_w,
                                                 const float* __restrict__ fc1_b,
                                                 const float* __restrict__ fc2_w,
                                                 const float* __restrict__ fc2_b,
                                                 const float* __restrict__ out_w,
                                                 const float* __restrict__ out_b,
                                                 float* __restrict__ out) {
    __shared__ float zs[256];
    __shared__ float h1[128];
    __shared__ float h2[64];
    int g = blockIdx.x;
    int t = threadIdx.x;

    float m = g_sumL[2][t] * (1.0f / NN);
    float va = g_sumsqL[2][t] * (1.0f / NN) - m * m;
    float sc = rsqrtf(va + 1e-5f) * gamma[t];
    float sh = beta[t] - m * sc;

    int s = g_gstart[g], e = g_gend[g];
    float sum = 0.f, mx = -3.4e38f;
    for (int n = s; n < e; n++) {
        float v = fmaxf(g_agg[(size_t)n * 128 + t] * sc + sh, 0.f);
        sum += v;
        mx = fmaxf(mx, v);
    }
    zs[t] = sum / (float)(e - s);
    zs[128 + t] = mx;
    __syncthreads();

    float acc = fc1_b[t];
#pragma unroll 8
    for (int k = 0; k < 256; k++) acc += zs[k] * fc1_w[k * 128 + t];
    h1[t] = fmaxf(acc, 0.f);
    __syncthreads();
    if (t < 64) {
        float a = fc2_b[t];
#pragma unroll 8
        for (int k = 0; k < 128; k++) a += h1[k] * fc2_w[k * 64 + t];
        h2[t] = fmaxf(a, 0.f);
    }
    __syncthreads();
    if (t < 5) {
        float a = out_b[t];
#pragma unroll
        for (int k = 0; k < 64; k++) a += h2[k] * out_w[k * 5 + t];
        out[g * 5 + t] = a;
    }
}

// ---------------- launch ----------------
extern "C" void kernel_launch(void* const* d_in, const int* in_sizes, int n_in,
                              void* d_out, int out_size) {
    const float* x = (const float*)d_in[0];
    const int* ei = (const int*)d_in[1];
    const int* src = ei;
    const int* dst = ei + EE;
    const int* batch = (const int*)d_in[2];
    const float* W0 = (const float*)d_in[3];
    const float* b0 = (const float*)d_in[4];
    const float* gm0 = (const float*)d_in[5];
    const float* be0 = (const float*)d_in[6];
    const float* W1 = (const float*)d_in[7];
    const float* b1 = (const float*)d_in[8];
    const float* gm1 = (const float*)d_in[9];
    const float* be1 = (const float*)d_in[10];
    const float* W2 = (const float*)d_in[11];
    const float* b2 = (const float*)d_in[12];
    const float* gm2 = (const float*)d_in[13];
    const float* be2 = (const float*)d_in[14];
    const float* fc1_w = (const float*)d_in[15];
    const float* fc1_b = (const float*)d_in[16];
    const float* fc2_w = (const float*)d_in[17];
    const float* fc2_b = (const float*)d_in[18];
    const float* out_w = (const float*)d_in[19];
    const float* out_b = (const float*)d_in[20];
    float* out = (float*)d_out;

    cudaFuncSetAttribute(k_tcgemm, cudaFuncAttributeMaxDynamicSharedMemorySize, SM_TOT);

    // CSR build + weight image prep
    k_init<<<(NN + 511) / 512, 512>>>();
    k_prepw<<<128, 256>>>(W1, W2);
    k_deg<<<(EE + 1023) / 1024, 1024>>>(dst);
    k_blocksum<<<NBLK2, 256>>>();
    k_scanoff<<<1, 256>>>();
    k_scanlocal<<<NBLK2, 256>>>();
    k_fill<<<(EE + 1023) / 1024, 1024>>>(src, dst);
    k_ranges<<<(NN + 511) / 512, 512>>>(batch);

    // layer 0
    k_gemm0<<<(NN + 7) / 8, 256>>>(x, W0);
    k_gather<<<NN / 8, 256>>>(b0, 0);
    // layer 1
    k_tcgemm<<<MBLK, 256, SM_TOT>>>(gm0, be0, 0, 0);
    k_gather<<<NN / 8, 256>>>(b1, 1);
    // layer 2
    k_tcgemm<<<MBLK, 256, SM_TOT>>>(gm1, be1, 1, 1);
    k_gather<<<NN / 8, 256>>>(b2, 2);

    // pool + head
    k_poolmlp<<<GG, 128>>>(gm2, be2, fc1_w, fc1_b, fc2_w, fc2_b,
                           out_w, out_b, out);
}